// round 15
// baseline (speedup 1.0000x reference)
#include <cuda_runtime.h>

#define B_  512
#define T_  2048
#define I_  33
#define H_  64
#define O_  2
#define BT_ (B_ * T_)
#define NEG2OVERLN2 -2.8853900817779268f

// Packed fp32x2 ops (Blackwell) — only reachable via PTX.
__device__ __forceinline__ void ffma2(float2& d, float2 a, float2 b) {
    asm("fma.rn.f32x2 %0, %1, %2, %0;"
        : "+l"(*reinterpret_cast<unsigned long long*>(&d))
        : "l"(*reinterpret_cast<const unsigned long long*>(&a)),
          "l"(*reinterpret_cast<const unsigned long long*>(&b)));
}
__device__ __forceinline__ float2 fadd2(float2 a, float2 b) {
    float2 r;
    asm("add.rn.f32x2 %0, %1, %2;"
        : "=l"(*reinterpret_cast<unsigned long long*>(&r))
        : "l"(*reinterpret_cast<const unsigned long long*>(&a)),
          "l"(*reinterpret_cast<const unsigned long long*>(&b)));
    return r;
}
__device__ __forceinline__ float ex2a(float x) {
    float y; asm("ex2.approx.f32 %0, %1;" : "=f"(y) : "f"(x)); return y;
}
__device__ __forceinline__ float rcpa(float x) {
    float y; asm("rcp.approx.f32 %0, %1;" : "=f"(y) : "f"(x)); return y;
}
// Input is PRE-SCALED: st = -2/ln2 * s. tanh(s) = 2/(1+2^st) - 1.
// ex2 overflow -> rcp(inf)=0 -> -1 (correct limit).
__device__ __forceinline__ float tanh_prescaled(float st) {
    float u = ex2a(st);
    float t = rcpa(1.0f + u);
    return fmaf(2.0f, t, -1.0f);
}

// ---------------- Phase 1: xt~ = c*(x @ W_ih^T + b_ih)  (into hidden region) ----------------
// R14 body; scale c folded into the staged weights/bias (zero extra cost).
#define XT_STRIDE 132   // pad: %4==0 (float4 align), %32==4 (bounded staging conflicts)
__global__ __launch_bounds__(256) void xw_kernel(
    const float* __restrict__ x, const float* __restrict__ W_ih,
    const float* __restrict__ b_ih, float* __restrict__ xw)
{
    __shared__ float Wc[I_ * H_];                 // col-major, pre-scaled by c
    __shared__ float bsh[H_];
    __shared__ __align__(16) float xt[I_ * XT_STRIDE];   // transposed: xt[i][row]

    int tid = threadIdx.x;
    int og  = tid >> 5;                           // output group (8 outputs), warp-uniform
    int rl4 = (tid & 31) * 4;                     // 4 rows per lane

    for (int e = tid; e < I_ * H_; e += 256) {
        int i = e >> 6, j = e & 63;
        Wc[e] = NEG2OVERLN2 * W_ih[j * I_ + i];
    }
    if (tid < H_) bsh[tid] = NEG2OVERLN2 * b_ih[tid];

    const float* xg = x + (size_t)blockIdx.x * 128 * I_;
    #pragma unroll
    for (int q = 0; q < 17; ++q) {
        int idx = tid + q * 256;
        if (idx < 128 * I_) {
            int row = idx / I_;
            int i   = idx - row * I_;
            xt[i * XT_STRIDE + row] = xg[idx];
        }
    }
    __syncthreads();

    float2 bloc[4];
    const float2* b2 = (const float2*)(bsh + og * 8);
    #pragma unroll
    for (int q = 0; q < 4; ++q) bloc[q] = b2[q];
    float2 acc[4][4];
    #pragma unroll
    for (int r = 0; r < 4; ++r)
        #pragma unroll
        for (int q = 0; q < 4; ++q) acc[r][q] = bloc[q];

    #pragma unroll
    for (int i = 0; i < I_; ++i) {
        float4 xv = *(const float4*)(xt + i * XT_STRIDE + rl4);        // conflict-free
        const float4* wr = (const float4*)(Wc + i * H_ + og * 8);      // uniform broadcast
        float4 w0 = wr[0], w1 = wr[1];
        float2 wp[4] = { make_float2(w0.x, w0.y), make_float2(w0.z, w0.w),
                         make_float2(w1.x, w1.y), make_float2(w1.z, w1.w) };
        float xr[4] = { xv.x, xv.y, xv.z, xv.w };
        #pragma unroll
        for (int r = 0; r < 4; ++r) {
            float2 x2 = make_float2(xr[r], xr[r]);
            #pragma unroll
            for (int q = 0; q < 4; ++q) ffma2(acc[r][q], wp[q], x2);
        }
    }

    size_t rowbase = (size_t)blockIdx.x * 128 + rl4;
    #pragma unroll
    for (int r = 0; r < 4; ++r) {
        float4* op = (float4*)(xw + (rowbase + r) * H_ + og * 8);
        op[0] = make_float4(acc[r][0].x, acc[r][0].y, acc[r][1].x, acc[r][1].y);
        op[1] = make_float4(acc[r][2].x, acc[r][2].y, acc[r][3].x, acc[r][3].y);
    }
}

// ---------------- Phase 2: recurrence, pair co-located on ONE SMSP ----------------
// wid%4 -> SMSP, so pair {wid, wid+4} shares a scheduler: bar.sync(64) release
// has minimal skew and the two warps are forced anti-phase. Weights/bias/x are
// pre-scaled by c so tanh needs no leading multiply.
__device__ __forceinline__ void rnn_step(
    const float4* __restrict__ hr, float* __restrict__ hw,
    const float2* __restrict__ w, float xb,
    float* __restrict__ outp, float* __restrict__ xp, const float* __restrict__ pfp,
    int j, int barid)
{
    float2 a0 = make_float2(xb, 0.f), a1 = make_float2(0.f, 0.f);
    float2 a2 = make_float2(0.f, 0.f), a3 = make_float2(0.f, 0.f);
    *xp = *pfp;                                   // re-issue prefetch (off path, consumed +4 steps)

    #pragma unroll
    for (int q = 0; q < 8; ++q) {                 // 32 FFMA2 (pre-scaled weights), 4 chains depth 8
        float4 h4a = hr[2 * q];
        float4 h4b = hr[2 * q + 1];
        ffma2(a0, w[4 * q],     make_float2(h4a.x, h4a.y));
        ffma2(a1, w[4 * q + 1], make_float2(h4a.z, h4a.w));
        ffma2(a2, w[4 * q + 2], make_float2(h4b.x, h4b.y));
        ffma2(a3, w[4 * q + 3], make_float2(h4b.z, h4b.w));
    }
    float2 s = fadd2(fadd2(a0, a1), fadd2(a2, a3));
    float hn = tanh_prescaled(s.x + s.y);

    hw[j]   = hn;                                 // STS.32 into next buffer (drained by bar)
    *outp   = hn;                                 // STG.32 output (off path)
    asm volatile("bar.sync %0, 64;" :: "r"(barid) : "memory");
}

__global__ __launch_bounds__(256, 1) void rnn_kernel(
    float* __restrict__ hs, const float* __restrict__ h0,
    const float* __restrict__ W_hh, const float* __restrict__ b_hh)
{
    __shared__ __align__(16) float hb[4][2][H_];   // [pair][buf][64]
    int wid  = threadIdx.x >> 5;
    int l    = threadIdx.x & 31;
    int pair = wid & 3;                            // == SMSP id (wid%4)
    int half = wid >> 2;                           // pair = {wid, wid+4} on same SMSP
    int row  = blockIdx.x * 4 + pair;
    int j    = half * 32 + l;                      // this lane's output index

    // W_hh row j as 32 k-pairs (64 regs), pre-scaled by c.
    float2 w[32];
    const float4* wr = (const float4*)(W_hh + j * H_);
    #pragma unroll
    for (int q = 0; q < 16; ++q) {
        float4 a = wr[q];
        w[2 * q]     = make_float2(NEG2OVERLN2 * a.x, NEG2OVERLN2 * a.y);
        w[2 * q + 1] = make_float2(NEG2OVERLN2 * a.z, NEG2OVERLN2 * a.w);
    }
    float bj = NEG2OVERLN2 * b_hh[j];

    hb[pair][0][j] = h0[row * H_ + j];

    float* base = hs + (size_t)row * T_ * H_ + j;  // lane-strided column pointer
    float xp[4];                                   // prefetch depth 4, RAW (bias deferred)
    #pragma unroll
    for (int k = 0; k < 4; ++k)
        xp[k] = base[k * H_];
    __syncthreads();                               // h0 halves visible across the pair

    int barid = pair + 1;                          // named barriers 1..4, 64 threads each

    // Main loop: t in [0, T-8), prefetch t+4 unclamped.
    for (int t = 0; t < T_ - 8; t += 4) {
        #pragma unroll
        for (int k = 0; k < 4; ++k) {
            int tt = t + k;
            rnn_step((const float4*)hb[pair][tt & 1], hb[pair][(tt + 1) & 1],
                     w, xp[k] + bj,
                     base + (size_t)tt * H_, &xp[k], base + (size_t)(tt + 4) * H_,
                     j, barid);
        }
    }
    // Tail: last 8 steps, prefetch clamped (never consumed past T-1).
    for (int t = T_ - 8; t < T_; t += 4) {
        #pragma unroll
        for (int k = 0; k < 4; ++k) {
            int tt = t + k;
            int tn = tt + 4; if (tn > T_ - 1) tn = T_ - 1;
            rnn_step((const float4*)hb[pair][tt & 1], hb[pair][(tt + 1) & 1],
                     w, xp[k] + bj,
                     base + (size_t)tt * H_, &xp[k], base + (size_t)tn * H_,
                     j, barid);
        }
    }
}

// ---------------- Phase 3: predictions = hs @ W_ro^T + b_ro ----------------
__global__ __launch_bounds__(256) void pred_kernel(
    const float* __restrict__ hs, const float* __restrict__ W_ro,
    const float* __restrict__ b_ro, float* __restrict__ pred)
{
    __shared__ float w0[H_], w1[H_];
    int tid = threadIdx.x;
    if (tid < H_) { w0[tid] = W_ro[tid]; w1[tid] = W_ro[H_ + tid]; }
    __syncthreads();

    size_t r = (size_t)blockIdx.x * 256 + tid;
    const float4* hp = (const float4*)(hs + r * H_);
    float p0a = 0.f, p0b = 0.f, p1a = 0.f, p1b = 0.f;
    #pragma unroll
    for (int q = 0; q < 16; ++q) {
        float4 h = hp[q];
        p0a += h.x * w0[4 * q]     + h.z * w0[4 * q + 2];
        p0b += h.y * w0[4 * q + 1] + h.w * w0[4 * q + 3];
        p1a += h.x * w1[4 * q]     + h.z * w1[4 * q + 2];
        p1b += h.y * w1[4 * q + 1] + h.w * w1[4 * q + 3];
    }
    ((float2*)pred)[r] = make_float2(p0a + p0b + b_ro[0], p1a + p1b + b_ro[1]);
}

extern "C" void kernel_launch(void* const* d_in, const int* in_sizes, int n_in,
                              void* d_out, int out_size)
{
    const float* x   = (const float*)d_in[0];
    const float* h0  = (const float*)d_in[1];
    const float* Wih = (const float*)d_in[2];
    const float* Whh = (const float*)d_in[3];
    const float* bih = (const float*)d_in[4];
    const float* bhh = (const float*)d_in[5];
    const float* Wro = (const float*)d_in[6];
    const float* bro = (const float*)d_in[7];

    float* out  = (float*)d_out;
    float* pred = out;                               // [B,T,O]
    float* hsb  = out + (size_t)B_ * T_ * O_;        // [B,T,H] — staged x~, overwritten with h

    xw_kernel  <<<BT_ / 128, 256>>>(x, Wih, bih, hsb);
    rnn_kernel <<<B_ / 4,    256>>>(hsb, h0, Whh, bhh);
    pred_kernel<<<BT_ / 256, 256>>>(hsb, Wro, bro, pred);
}

// round 16
// speedup vs baseline: 1.0354x; 1.0354x over previous
#include <cuda_runtime.h>

#define B_  512
#define T_  2048
#define I_  33
#define H_  64
#define O_  2
#define BT_ (B_ * T_)
#define NEG2OVERLN2 -2.8853900817779268f

// Packed fp32x2 ops (Blackwell) — only reachable via PTX.
__device__ __forceinline__ void ffma2(float2& d, float2 a, float2 b) {
    asm("fma.rn.f32x2 %0, %1, %2, %0;"
        : "+l"(*reinterpret_cast<unsigned long long*>(&d))
        : "l"(*reinterpret_cast<const unsigned long long*>(&a)),
          "l"(*reinterpret_cast<const unsigned long long*>(&b)));
}
__device__ __forceinline__ float2 fadd2(float2 a, float2 b) {
    float2 r;
    asm("add.rn.f32x2 %0, %1, %2;"
        : "=l"(*reinterpret_cast<unsigned long long*>(&r))
        : "l"(*reinterpret_cast<const unsigned long long*>(&a)),
          "l"(*reinterpret_cast<const unsigned long long*>(&b)));
    return r;
}
__device__ __forceinline__ float ex2a(float x) {
    float y; asm("ex2.approx.f32 %0, %1;" : "=f"(y) : "f"(x)); return y;
}
__device__ __forceinline__ float rcpa(float x) {
    float y; asm("rcp.approx.f32 %0, %1;" : "=f"(y) : "f"(x)); return y;
}
// Input is PRE-SCALED: st = -2/ln2 * s. tanh(s) = 2/(1+2^st) - 1.
// ex2 overflow -> rcp(inf)=0 -> -1 (correct limit).
__device__ __forceinline__ float tanh_prescaled(float st) {
    float u = ex2a(st);
    float t = rcpa(1.0f + u);
    return fmaf(2.0f, t, -1.0f);
}

// ---------------- Phase 1: xt~ = c*(x @ W_ih^T + b_ih)  (into hidden region) ----------------
// Exact R14 body (proven 159.8us); scale c folded into staged weights/bias (free).
#define XT_STRIDE 132   // pad: %4==0 (float4 align), %32==4 (bounded staging conflicts)
__global__ __launch_bounds__(256) void xw_kernel(
    const float* __restrict__ x, const float* __restrict__ W_ih,
    const float* __restrict__ b_ih, float* __restrict__ xw)
{
    __shared__ float Wc[I_ * H_];                 // col-major, pre-scaled by c
    __shared__ float bsh[H_];
    __shared__ __align__(16) float xt[I_ * XT_STRIDE];   // transposed: xt[i][row]

    int tid = threadIdx.x;
    int og  = tid >> 5;                           // output group (8 outputs), warp-uniform
    int rl4 = (tid & 31) * 4;                     // 4 rows per lane

    for (int e = tid; e < I_ * H_; e += 256) {
        int i = e >> 6, j = e & 63;
        Wc[e] = NEG2OVERLN2 * W_ih[j * I_ + i];
    }
    if (tid < H_) bsh[tid] = NEG2OVERLN2 * b_ih[tid];

    const float* xg = x + (size_t)blockIdx.x * 128 * I_;
    #pragma unroll
    for (int q = 0; q < 17; ++q) {
        int idx = tid + q * 256;
        if (idx < 128 * I_) {
            int row = idx / I_;
            int i   = idx - row * I_;
            xt[i * XT_STRIDE + row] = xg[idx];
        }
    }
    __syncthreads();

    float2 bloc[4];
    const float2* b2 = (const float2*)(bsh + og * 8);
    #pragma unroll
    for (int q = 0; q < 4; ++q) bloc[q] = b2[q];
    float2 acc[4][4];
    #pragma unroll
    for (int r = 0; r < 4; ++r)
        #pragma unroll
        for (int q = 0; q < 4; ++q) acc[r][q] = bloc[q];

    #pragma unroll
    for (int i = 0; i < I_; ++i) {
        float4 xv = *(const float4*)(xt + i * XT_STRIDE + rl4);        // conflict-free
        const float4* wr = (const float4*)(Wc + i * H_ + og * 8);      // uniform broadcast
        float4 w0 = wr[0], w1 = wr[1];
        float2 wp[4] = { make_float2(w0.x, w0.y), make_float2(w0.z, w0.w),
                         make_float2(w1.x, w1.y), make_float2(w1.z, w1.w) };
        float xr[4] = { xv.x, xv.y, xv.z, xv.w };
        #pragma unroll
        for (int r = 0; r < 4; ++r) {
            float2 x2 = make_float2(xr[r], xr[r]);
            #pragma unroll
            for (int q = 0; q < 4; ++q) ffma2(acc[r][q], wp[q], x2);
        }
    }

    size_t rowbase = (size_t)blockIdx.x * 128 + rl4;
    #pragma unroll
    for (int r = 0; r < 4; ++r) {
        float4* op = (float4*)(xw + (rowbase + r) * H_ + og * 8);
        op[0] = make_float4(acc[r][0].x, acc[r][0].y, acc[r][1].x, acc[r][1].y);
        op[1] = make_float4(acc[r][2].x, acc[r][2].y, acc[r][3].x, acc[r][3].y);
    }
}

// ---------------- Phase 2: recurrence — R14 body + prescale ----------------
// pair = wid>>1 (R14 mapping, PROVEN: each SMSP hosts warps of two DIFFERENT rows,
// so barrier waits are filled by independent work; R15 showed co-locating a pair
// on one SMSP removes that independence and regresses).
__device__ __forceinline__ void rnn_step(
    const float4* __restrict__ hr, float* __restrict__ hw,
    const float2* __restrict__ w, float xb,
    float* __restrict__ outp, float* __restrict__ xp, const float* __restrict__ pfp,
    int j, int barid)
{
    float2 a0 = make_float2(xb, 0.f), a1 = make_float2(0.f, 0.f);
    float2 a2 = make_float2(0.f, 0.f), a3 = make_float2(0.f, 0.f);
    *xp = *pfp;                                   // re-issue prefetch (off path, consumed +4 steps)

    #pragma unroll
    for (int q = 0; q < 8; ++q) {                 // 32 FFMA2 (pre-scaled weights), 4 chains depth 8
        float4 h4a = hr[2 * q];
        float4 h4b = hr[2 * q + 1];
        ffma2(a0, w[4 * q],     make_float2(h4a.x, h4a.y));
        ffma2(a1, w[4 * q + 1], make_float2(h4a.z, h4a.w));
        ffma2(a2, w[4 * q + 2], make_float2(h4b.x, h4b.y));
        ffma2(a3, w[4 * q + 3], make_float2(h4b.z, h4b.w));
    }
    float2 s = fadd2(fadd2(a0, a1), fadd2(a2, a3));
    float hn = tanh_prescaled(s.x + s.y);

    hw[j]   = hn;                                 // STS.32 into next buffer (drained by bar)
    *outp   = hn;                                 // STG.32 output (off path)
    asm volatile("bar.sync %0, 64;" :: "r"(barid) : "memory");
}

__global__ __launch_bounds__(256, 1) void rnn_kernel(
    float* __restrict__ hs, const float* __restrict__ h0,
    const float* __restrict__ W_hh, const float* __restrict__ b_hh)
{
    __shared__ __align__(16) float hb[4][2][H_];   // [pair][buf][64]
    int wid  = threadIdx.x >> 5;
    int l    = threadIdx.x & 31;
    int pair = wid >> 1;                           // R14 mapping (pair warps on different SMSPs)
    int half = wid & 1;
    int row  = blockIdx.x * 4 + pair;
    int j    = half * 32 + l;                      // this lane's output index

    // W_hh row j as 32 k-pairs (64 regs), pre-scaled by c.
    float2 w[32];
    const float4* wr = (const float4*)(W_hh + j * H_);
    #pragma unroll
    for (int q = 0; q < 16; ++q) {
        float4 a = wr[q];
        w[2 * q]     = make_float2(NEG2OVERLN2 * a.x, NEG2OVERLN2 * a.y);
        w[2 * q + 1] = make_float2(NEG2OVERLN2 * a.z, NEG2OVERLN2 * a.w);
    }
    float bj = NEG2OVERLN2 * b_hh[j];

    hb[pair][0][j] = h0[row * H_ + j];

    float* base = hs + (size_t)row * T_ * H_ + j;  // lane-strided column pointer
    float xp[4];                                   // prefetch depth 4, RAW (bias deferred)
    #pragma unroll
    for (int k = 0; k < 4; ++k)
        xp[k] = base[k * H_];
    __syncthreads();                               // h0 halves visible across the pair

    int barid = pair + 1;                          // named barriers 1..4, 64 threads each

    // Main loop: t in [0, T-8), prefetch t+4 unclamped.
    for (int t = 0; t < T_ - 8; t += 4) {
        #pragma unroll
        for (int k = 0; k < 4; ++k) {
            int tt = t + k;
            rnn_step((const float4*)hb[pair][tt & 1], hb[pair][(tt + 1) & 1],
                     w, xp[k] + bj,
                     base + (size_t)tt * H_, &xp[k], base + (size_t)(tt + 4) * H_,
                     j, barid);
        }
    }
    // Tail: last 8 steps, prefetch clamped (never consumed past T-1).
    for (int t = T_ - 8; t < T_; t += 4) {
        #pragma unroll
        for (int k = 0; k < 4; ++k) {
            int tt = t + k;
            int tn = tt + 4; if (tn > T_ - 1) tn = T_ - 1;
            rnn_step((const float4*)hb[pair][tt & 1], hb[pair][(tt + 1) & 1],
                     w, xp[k] + bj,
                     base + (size_t)tt * H_, &xp[k], base + (size_t)tn * H_,
                     j, barid);
        }
    }
}

// ---------------- Phase 3: predictions = hs @ W_ro^T + b_ro ----------------
__global__ __launch_bounds__(256) void pred_kernel(
    const float* __restrict__ hs, const float* __restrict__ W_ro,
    const float* __restrict__ b_ro, float* __restrict__ pred)
{
    __shared__ float w0[H_], w1[H_];
    int tid = threadIdx.x;
    if (tid < H_) { w0[tid] = W_ro[tid]; w1[tid] = W_ro[H_ + tid]; }
    __syncthreads();

    size_t r = (size_t)blockIdx.x * 256 + tid;
    const float4* hp = (const float4*)(hs + r * H_);
    float p0a = 0.f, p0b = 0.f, p1a = 0.f, p1b = 0.f;
    #pragma unroll
    for (int q = 0; q < 16; ++q) {
        float4 h = hp[q];
        p0a += h.x * w0[4 * q]     + h.z * w0[4 * q + 2];
        p0b += h.y * w0[4 * q + 1] + h.w * w0[4 * q + 3];
        p1a += h.x * w1[4 * q]     + h.z * w1[4 * q + 2];
        p1b += h.y * w1[4 * q + 1] + h.w * w1[4 * q + 3];
    }
    ((float2*)pred)[r] = make_float2(p0a + p0b + b_ro[0], p1a + p1b + b_ro[1]);
}

extern "C" void kernel_launch(void* const* d_in, const int* in_sizes, int n_in,
                              void* d_out, int out_size)
{
    const float* x   = (const float*)d_in[0];
    const float* h0  = (const float*)d_in[1];
    const float* Wih = (const float*)d_in[2];
    const float* Whh = (const float*)d_in[3];
    const float* bih = (const float*)d_in[4];
    const float* bhh = (const float*)d_in[5];
    const float* Wro = (const float*)d_in[6];
    const float* bro = (const float*)d_in[7];

    float* out  = (float*)d_out;
    float* pred = out;                               // [B,T,O]
    float* hsb  = out + (size_t)B_ * T_ * O_;        // [B,T,H] — staged x~, overwritten with h

    xw_kernel  <<<BT_ / 128, 256>>>(x, Wih, bih, hsb);
    rnn_kernel <<<B_ / 4,    256>>>(hsb, h0, Whh, bhh);
    pred_kernel<<<BT_ / 256, 256>>>(hsb, Wro, bro, pred);
}